// round 1
// baseline (speedup 1.0000x reference)
#include <cuda_runtime.h>
#include <cstdint>

// Problem constants
#define KTOT  8192
#define WNUM  32
#define TDIM  512
#define FNUM  12
#define VDIM  512
#define BATCH 8

// Phase-1 tiling
#define NCHUNK 32
#define KC     (KTOT / NCHUNK)   // 256 k per chunk
#define DTILE  64
#define NDTILE (TDIM / DTILE)    // 8

// Partial argmin results per (chunk, b, d)
__device__ float g_pval[NCHUNK][BATCH][TDIM];
__device__ int   g_pidx[NCHUNK][BATCH][TDIM];

// Refined log2: y0 = lg2.approx(x); correction via ex2.
// l = y0 + (x*2^-y0 - 1)/ln2.  Abs error ~3e-7, cost 2 MUFU + 3 FMA-pipe ops.
__device__ __forceinline__ float flg2(float x) {
    float y0, t;
    asm("lg2.approx.f32 %0, %1;" : "=f"(y0) : "f"(x));
    float ny = -y0;
    asm("ex2.approx.f32 %0, %1;" : "=f"(t) : "f"(ny));
    float e = x * t;                       // ~= 1
    const float C = 1.4426950408889634f;   // 1/ln2
    return fmaf(e, C, y0 - C);
}

__device__ __forceinline__ unsigned long long pk2(float a, float b) {
    unsigned long long r;
    asm("mov.b64 %0, {%1, %2};" : "=l"(r) : "f"(a), "f"(b));
    return r;
}
__device__ __forceinline__ void upk2(unsigned long long v, float& a, float& b) {
    asm("mov.b64 {%0, %1}, %2;" : "=f"(a), "=f"(b) : "l"(v));
}
// packed fp32x2 FMA (Blackwell): r = a*b + c elementwise
__device__ __forceinline__ unsigned long long ffma2(unsigned long long a,
                                                    unsigned long long b,
                                                    unsigned long long c) {
    unsigned long long r;
    asm("fma.rn.f32x2 %0, %1, %2, %3;" : "=l"(r) : "l"(a), "l"(b), "l"(c));
    return r;
}

// ---------------------------------------------------------------------------
// Phase 1: for each (chunk, d-tile): scan k in chunk, maintain per-(b,d)
// running argmin of  sum_w qt*lg2(qt) - sum_w qt*lg2(q)   (scaled KL).
//
// Thread layout (256 threads):
//   lane = g*8 + ds   : g = w-octet group (0..3), ds = d sub-index (0..7)
//   warp w_id (0..7)  : d_local = w_id*8 + ds  -> 64 d per CTA
// Each thread: one d column, 8 consecutive w (w = g*8 .. g*8+7).
// lq[b][w] for its (d, w-octet) cached in registers as 32 f32x2.
// Per k: 8 loads, 8 refined logs, packed cross FMAs, then a 4-lane
// butterfly (xor 8, xor 16) to reduce the 8 per-b objectives, and a
// redundant (all-lane) min/argmin update.
// ---------------------------------------------------------------------------
__global__ __launch_bounds__(256, 2)
void knw_phase1(const float* __restrict__ query,
                const float* __restrict__ qtext) {
    const int chunk = blockIdx.x;     // 0..NCHUNK-1
    const int dt    = blockIdx.y;     // 0..NDTILE-1
    const int tid   = threadIdx.x;
    const int lane  = tid & 31;
    const int g     = lane >> 3;      // w-group 0..3
    const int ds    = lane & 7;
    const int w_id  = tid >> 5;       // warp in CTA 0..7
    const int dl    = w_id * 8 + ds;  // 0..63
    const int d     = dt * DTILE + dl;
    const int w0    = g * 8;

    // Cache lg2(query[b][w][d]) for this thread's 8 w, all 8 b, packed in pairs.
    unsigned long long lq2[4][8];
    #pragma unroll
    for (int j = 0; j < 8; j++) {
        const int w = w0 + j;
        #pragma unroll
        for (int bp = 0; bp < 4; bp++) {
            float a = flg2(query[((2 * bp)     * WNUM + w) * TDIM + d]);
            float b = flg2(query[((2 * bp + 1) * WNUM + w) * TDIM + d]);
            lq2[bp][j] = pk2(a, b);
        }
    }

    float minv[8];
    int   mini[8];
    #pragma unroll
    for (int i = 0; i < 8; i++) { minv[i] = __int_as_float(0x7f800000); mini[i] = 0; }

    const float* base = qtext + (size_t)(chunk * KC) * (WNUM * TDIM)
                              + (size_t)w0 * TDIM + d;

    #pragma unroll 1
    for (int kk = 0; kk < KC; kk++) {
        const float* p = base + (size_t)kk * (WNUM * TDIM);
        float x[8];
        #pragma unroll
        for (int j = 0; j < 8; j++) x[j] = p[j * TDIM];   // coalesced over ds

        float s = 0.0f;                                   // sum x*lg2(x)
        unsigned long long c2[4];
        #pragma unroll
        for (int bp = 0; bp < 4; bp++) c2[bp] = 0ull;

        #pragma unroll
        for (int j = 0; j < 8; j++) {
            const float xv = x[j];
            const float l  = flg2(xv);
            s = fmaf(xv, l, s);
            const unsigned long long xx = pk2(xv, xv);
            #pragma unroll
            for (int bp = 0; bp < 4; bp++)
                c2[bp] = ffma2(xx, lq2[bp][j], c2[bp]);
        }

        // Per-thread partial objective per b:  o_b = s_partial - c_b_partial
        float o[8];
        #pragma unroll
        for (int bp = 0; bp < 4; bp++) {
            float ca, cb;
            upk2(c2[bp], ca, cb);
            o[2 * bp]     = s - ca;
            o[2 * bp + 1] = s - cb;
        }

        // Butterfly reduce across the 4 w-groups (lanes xor 8, xor 16)
        #pragma unroll
        for (int i = 0; i < 8; i++) o[i] += __shfl_xor_sync(0xffffffffu, o[i], 8);
        #pragma unroll
        for (int i = 0; i < 8; i++) o[i] += __shfl_xor_sync(0xffffffffu, o[i], 16);

        const int kglob = chunk * KC + kk;
        #pragma unroll
        for (int i = 0; i < 8; i++) {
            bool pmin = o[i] < minv[i];          // strict < keeps earliest k
            minv[i] = pmin ? o[i]  : minv[i];
            mini[i] = pmin ? kglob : mini[i];
        }
    }

    // All 4 g-lanes hold identical results; g==0 lanes write all 8 b.
    if (g == 0) {
        #pragma unroll
        for (int b = 0; b < 8; b++) {
            g_pval[chunk][b][d] = minv[b];
            g_pidx[chunk][b][d] = mini[b];
        }
    }
}

// ---------------------------------------------------------------------------
// Phase 2: one CTA per (b,d). Reduce the NCHUNK partial argmins (chunk order
// ascending + strict < preserves first-occurrence tie-break), then gather
// queue_video[idx] (12*512 floats) with float4 copies.
// ---------------------------------------------------------------------------
__global__ __launch_bounds__(256)
void knw_phase2(const float* __restrict__ qvideo, float* __restrict__ out) {
    const int bd = blockIdx.x;            // b*512 + d
    const int b  = bd >> 9;
    const int d  = bd & 511;

    __shared__ int sidx;
    if (threadIdx.x == 0) {
        float bv = __int_as_float(0x7f800000);
        int   bi = 0;
        #pragma unroll
        for (int c = 0; c < NCHUNK; c++) {
            float v = g_pval[c][b][d];
            int   i = g_pidx[c][b][d];
            if (v < bv) { bv = v; bi = i; }
        }
        sidx = bi;
    }
    __syncthreads();

    const int k = sidx;
    const float4* __restrict__ src =
        (const float4*)(qvideo + (size_t)k * (FNUM * VDIM));
    float4* __restrict__ dst = (float4*)(out + (size_t)bd * (FNUM * VDIM));
    #pragma unroll
    for (int i = threadIdx.x; i < (FNUM * VDIM) / 4; i += 256)
        dst[i] = src[i];
}

extern "C" void kernel_launch(void* const* d_in, const int* in_sizes, int n_in,
                              void* d_out, int out_size) {
    const float* query  = (const float*)d_in[0];   // [8, 32, 512]
    const float* qtext  = (const float*)d_in[1];   // [8192, 32, 512]
    const float* qvideo = (const float*)d_in[2];   // [8192, 12, 512]
    float* out = (float*)d_out;                    // [8, 512, 12, 512]

    dim3 g1(NCHUNK, NDTILE);
    knw_phase1<<<g1, 256>>>(query, qtext);
    knw_phase2<<<BATCH * TDIM, 256>>>(qvideo, out);
}

// round 4
// speedup vs baseline: 1.5190x; 1.5190x over previous
#include <cuda_runtime.h>
#include <cstdint>

// Problem constants
#define KTOT  8192
#define WNUM  32
#define TDIM  512
#define FNUM  12
#define VDIM  512
#define BATCH 8

// Phase-1 tiling
#define NCHUNK 32
#define KC     (KTOT / NCHUNK)    // 256 k per chunk
#define DTILE  64
#define NDTILE (TDIM / DTILE)     // 8
#define STAGE_K 2
#define NSTAGE (KC / STAGE_K)     // 128
#define TILE_F (WNUM * DTILE)     // 2048 floats = 8KB per k

// Partial argmin results per (chunk, b, d)
__device__ float g_pval[NCHUNK][BATCH][TDIM];
__device__ int   g_pidx[NCHUNK][BATCH][TDIM];
__device__ int   g_idx[BATCH * TDIM];

// Refined log2: y0 = lg2.approx(x); l = y0 + (x*2^-y0 - 1)/ln2.
__device__ __forceinline__ float flg2(float x) {
    float y0, t;
    asm("lg2.approx.f32 %0, %1;" : "=f"(y0) : "f"(x));
    float ny = -y0;
    asm("ex2.approx.f32 %0, %1;" : "=f"(t) : "f"(ny));
    float e = x * t;
    const float C = 1.4426950408889634f;
    return fmaf(e, C, y0 - C);
}

__device__ __forceinline__ unsigned long long pk2(float a, float b) {
    unsigned long long r;
    asm("mov.b64 %0, {%1, %2};" : "=l"(r) : "f"(a), "f"(b));
    return r;
}
__device__ __forceinline__ void upk2(unsigned long long v, float& a, float& b) {
    asm("mov.b64 {%0, %1}, %2;" : "=f"(a), "=f"(b) : "l"(v));
}
__device__ __forceinline__ unsigned long long ffma2(unsigned long long a,
                                                    unsigned long long b,
                                                    unsigned long long c) {
    unsigned long long r;
    asm("fma.rn.f32x2 %0, %1, %2, %3;" : "=l"(r) : "l"(a), "l"(b), "l"(c));
    return r;
}

#define CP16(dst, src) \
    asm volatile("cp.async.cg.shared.global [%0], [%1], 16;" :: "r"(dst), "l"(src))

// ---------------------------------------------------------------------------
// Phase 1: CTA = (k-chunk of 256, d-tile of 64). cp.async stages the
// [32w x 64d] fp32 tile per k into shared memory with a per-w-group rotation
// (row w stored rotated by 8*(w>>3) floats) so the 4 w-groups of a warp read
// 32 distinct banks. Thread layout: lane = g*8 + ds (g = w-octet, ds = d sub),
// warp covers 8 d, thread owns 8 w x 8 b with query logs cached in registers.
// Per k: 8 LDS, 8 refined logs, packed b-pair FMAs, split butterfly (keeps a
// 4-b half per lane), running argmin.
// ---------------------------------------------------------------------------
__global__ __launch_bounds__(256, 2)
void knw_phase1(const float* __restrict__ query,
                const float* __restrict__ qtext) {
    __shared__ float tile[2][STAGE_K][TILE_F];   // 32 KB

    const int chunk = blockIdx.x;
    const int dt    = blockIdx.y;
    const int tid   = threadIdx.x;
    const int lane  = tid & 31;
    const int g     = lane >> 3;
    const int ds    = lane & 7;
    const int w_id  = tid >> 5;
    const int dl    = w_id * 8 + ds;
    const int d     = dt * DTILE + dl;
    const int w0    = g * 8;
    const int bh    = g & 1;                     // b-half owned after reduction

    // Cache refined lg2(query[b][w][d]) for this thread's 8 w, 8 b (packed).
    unsigned long long lq2[4][8];
    #pragma unroll
    for (int j = 0; j < 8; j++) {
        const int w = w0 + j;
        #pragma unroll
        for (int bp = 0; bp < 4; bp++) {
            float a = flg2(query[((2 * bp)     * WNUM + w) * TDIM + d]);
            float b = flg2(query[((2 * bp + 1) * WNUM + w) * TDIM + d]);
            lq2[bp][j] = pk2(a, b);
        }
    }

    // Staging assignment: thread handles 16B chunks m = tid, tid+256 per k.
    const int w_a = tid >> 4,        c_a = tid & 15;
    const int w_b = (tid + 256) >> 4, c_b = (tid + 256) & 15;
    // dst byte offsets within one k-tile (rotation in 16B-chunk units)
    const int doff_a = (w_a * 64 + (((c_a + 2 * (w_a >> 3)) & 15) << 2)) * 4;
    const int doff_b = (w_b * 64 + (((c_b + 2 * (w_b >> 3)) & 15) << 2)) * 4;
    // src byte offsets within one k-row of qtext
    const long soff_a = ((long)w_a * TDIM + dt * DTILE + c_a * 4) * 4;
    const long soff_b = ((long)w_b * TDIM + dt * DTILE + c_b * 4) * 4;

    const char* kbase = (const char*)(qtext + (size_t)(chunk * KC) * (WNUM * TDIM));
    const unsigned tile_u32 = (unsigned)__cvta_generic_to_shared(tile);
    const long KROW = (long)WNUM * TDIM * 4;     // bytes per k

    auto issue_stage = [&](int s) {
        const int buf = s & 1;
        const char* src = kbase + (long)(s * STAGE_K) * KROW;
        const unsigned dbase = tile_u32 + buf * (STAGE_K * TILE_F * 4);
        #pragma unroll
        for (int ki = 0; ki < STAGE_K; ki++) {
            CP16(dbase + ki * (TILE_F * 4) + doff_a, src + ki * KROW + soff_a);
            CP16(dbase + ki * (TILE_F * 4) + doff_b, src + ki * KROW + soff_b);
        }
        asm volatile("cp.async.commit_group;");
    };

    issue_stage(0);

    float minv[4];
    int   mini[4];
    #pragma unroll
    for (int i = 0; i < 4; i++) { minv[i] = __int_as_float(0x7f800000); mini[i] = 0; }

    const int pbase = g * 512 + ((dl + 8 * g) & 63);   // LDS base (floats)

    #pragma unroll 1
    for (int s = 0; s < NSTAGE; s++) {
        if (s + 1 < NSTAGE) {
            issue_stage(s + 1);
            asm volatile("cp.async.wait_group 1;");
        } else {
            asm volatile("cp.async.wait_group 0;");
        }
        __syncthreads();

        #pragma unroll
        for (int ki = 0; ki < STAGE_K; ki++) {
            const float* tp = &tile[s & 1][ki][0];

            float x[8];
            #pragma unroll
            for (int j = 0; j < 8; j++) x[j] = tp[pbase + j * 64];

            float sacc = 0.0f;
            unsigned long long c2[4];
            #pragma unroll
            for (int bp = 0; bp < 4; bp++) c2[bp] = 0ull;

            #pragma unroll
            for (int j = 0; j < 8; j++) {
                const float xv = x[j];
                const float l  = flg2(xv);
                sacc = fmaf(xv, l, sacc);
                const unsigned long long xx = pk2(xv, xv);
                #pragma unroll
                for (int bp = 0; bp < 4; bp++)
                    c2[bp] = ffma2(xx, lq2[bp][j], c2[bp]);
            }

            float o[8];
            #pragma unroll
            for (int bp = 0; bp < 4; bp++) {
                float ca, cb;
                upk2(c2[bp], ca, cb);
                o[2 * bp]     = sacc - ca;
                o[2 * bp + 1] = sacc - cb;
            }

            // Round 1 (xor 8): each lane keeps the b-half selected by bh.
            float h[4];
            #pragma unroll
            for (int i = 0; i < 4; i++) {
                float tlo = __shfl_xor_sync(0xffffffffu, o[i],     8);
                float thi = __shfl_xor_sync(0xffffffffu, o[4 + i], 8);
                float lo = o[i] + tlo;
                float hi = o[4 + i] + thi;
                h[i] = bh ? hi : lo;
            }
            // Round 2 (xor 16): partner has the same b-half.
            #pragma unroll
            for (int i = 0; i < 4; i++)
                h[i] += __shfl_xor_sync(0xffffffffu, h[i], 16);

            const int kglob = chunk * KC + s * STAGE_K + ki;
            #pragma unroll
            for (int i = 0; i < 4; i++) {
                bool pmin = h[i] < minv[i];
                minv[i] = pmin ? h[i]  : minv[i];
                mini[i] = pmin ? kglob : mini[i];
            }
        }
        __syncthreads();
    }

    // Lanes g==0 hold b 0..3, g==1 hold b 4..7 (g==2,3 are duplicates).
    if (g < 2) {
        #pragma unroll
        for (int i = 0; i < 4; i++) {
            g_pval[chunk][bh * 4 + i][d] = minv[i];
            g_pidx[chunk][bh * 4 + i][d] = mini[i];
        }
    }
}

// ---------------------------------------------------------------------------
// Phase 2a: reduce NCHUNK partial argmins -> g_idx[b*512+d].
// Chunk order ascending + strict < preserves first-occurrence tie-break.
// ---------------------------------------------------------------------------
__global__ __launch_bounds__(256)
void knw_phase2a() {
    const int bd = blockIdx.x * 256 + threadIdx.x;   // 0..4095
    const int b  = bd >> 9;
    const int d  = bd & 511;
    float bv = __int_as_float(0x7f800000);
    int   bi = 0;
    #pragma unroll
    for (int c = 0; c < NCHUNK; c++) {
        float v = g_pval[c][b][d];
        int   i = g_pidx[c][b][d];
        if (v < bv) { bv = v; bi = i; }
    }
    g_idx[bd] = bi;
}

// ---------------------------------------------------------------------------
// Phase 2b: pure gather-copy. One float4 per thread.
// out[bd][0..1535 float4] = qvideo[g_idx[bd]][...]
// ---------------------------------------------------------------------------
__global__ __launch_bounds__(256)
void knw_phase2b(const float* __restrict__ qvideo, float* __restrict__ out) {
    const int gid = blockIdx.x * 256 + threadIdx.x;  // 0..6291455
    const int bd  = gid / 1536;
    const int r   = gid - bd * 1536;
    const int k   = g_idx[bd];
    const float4* __restrict__ src = (const float4*)qvideo;
    float4* __restrict__ dst = (float4*)out;
    dst[gid] = src[(size_t)k * 1536 + r];
}

extern "C" void kernel_launch(void* const* d_in, const int* in_sizes, int n_in,
                              void* d_out, int out_size) {
    const float* query  = (const float*)d_in[0];   // [8, 32, 512]
    const float* qtext  = (const float*)d_in[1];   // [8192, 32, 512]
    const float* qvideo = (const float*)d_in[2];   // [8192, 12, 512]
    float* out = (float*)d_out;                    // [8, 512, 12, 512]

    dim3 g1(NCHUNK, NDTILE);
    knw_phase1<<<g1, 256>>>(query, qtext);
    knw_phase2a<<<BATCH * TDIM / 256, 256>>>();
    knw_phase2b<<<(BATCH * TDIM * FNUM * VDIM / 4) / 256, 256>>>(qvideo, out);
}

// round 5
// speedup vs baseline: 1.7402x; 1.1456x over previous
#include <cuda_runtime.h>
#include <cstdint>

// Problem constants
#define KTOT  8192
#define WNUM  32
#define TDIM  512
#define FNUM  12
#define VDIM  512
#define BATCH 8

// Phase-1 tiling
#define NCHUNK 32
#define KC     (KTOT / NCHUNK)    // 256 k per chunk
#define DTILE  64
#define NDTILE (TDIM / DTILE)     // 8
#define STAGE_K 4
#define NSTAGE (KC / STAGE_K)     // 64
#define TILE_F (WNUM * DTILE)     // 2048 floats = 8KB per k
#define SMEM_BYTES (2 * STAGE_K * TILE_F * 4)   // 64 KB

// Partial argmin results per (chunk, b, d)
__device__ float g_pval[NCHUNK][BATCH][TDIM];
__device__ int   g_pidx[NCHUNK][BATCH][TDIM];
__device__ int   g_idx[BATCH * TDIM];

// Exact-exponent log2: split x = m * 2^e (m in [1,2)), l = lg2.approx(m) + e.
// lg2.approx abs error on [1,2) is ~1.5e-7; e exact. 1 MUFU, short dep chain.
__device__ __forceinline__ float flg2(float x) {
    int bi = __float_as_int(x);
    float m = __int_as_float((bi & 0x007fffff) | 0x3f800000);
    float e = (float)((bi >> 23) - 127);
    float lm;
    asm("lg2.approx.f32 %0, %1;" : "=f"(lm) : "f"(m));
    return lm + e;
}

__device__ __forceinline__ unsigned long long pk2(float a, float b) {
    unsigned long long r;
    asm("mov.b64 %0, {%1, %2};" : "=l"(r) : "f"(a), "f"(b));
    return r;
}
__device__ __forceinline__ void upk2(unsigned long long v, float& a, float& b) {
    asm("mov.b64 {%0, %1}, %2;" : "=f"(a), "=f"(b) : "l"(v));
}
__device__ __forceinline__ unsigned long long ffma2(unsigned long long a,
                                                    unsigned long long b,
                                                    unsigned long long c) {
    unsigned long long r;
    asm("fma.rn.f32x2 %0, %1, %2, %3;" : "=l"(r) : "l"(a), "l"(b), "l"(c));
    return r;
}
__device__ __forceinline__ unsigned long long fadd2(unsigned long long a,
                                                    unsigned long long b) {
    unsigned long long r;
    asm("add.rn.f32x2 %0, %1, %2;" : "=l"(r) : "l"(a), "l"(b));
    return r;
}

#define CP16(dst, src) \
    asm volatile("cp.async.cg.shared.global [%0], [%1], 16;" :: "r"(dst), "l"(src))

// ---------------------------------------------------------------------------
// Phase 1: CTA = (k-chunk of 256, d-tile of 64). cp.async stages 4 k-rows of
// the [32w x 64d] fp32 tile per stage into rotated shared memory (row w
// rotated by 8*(w>>3) floats -> 4 w-groups of a warp hit 32 distinct banks).
// lane = g*8 + ds (g = w-octet, ds = d sub); thread owns one d, 8 w, 8 b with
// NEGATED query logs cached packed in registers.
// Per k: 8 LDS, 8 one-MUFU logs, packed b-pair FMAs, o = sacc + c (packed),
// half-exchange butterfly (r1 sends only the partner's b-half), argmin.
// ---------------------------------------------------------------------------
__global__ __launch_bounds__(256, 2)
void knw_phase1(const float* __restrict__ query,
                const float* __restrict__ qtext) {
    extern __shared__ float tile[];              // [2][STAGE_K][TILE_F]

    const int chunk = blockIdx.x;
    const int dt    = blockIdx.y;
    const int tid   = threadIdx.x;
    const int lane  = tid & 31;
    const int g     = lane >> 3;
    const int ds    = lane & 7;
    const int w_id  = tid >> 5;
    const int dl    = w_id * 8 + ds;
    const int d     = dt * DTILE + dl;
    const int w0    = g * 8;
    const int bh    = g & 1;                     // b-half owned after reduction

    // Cache NEGATED lg2(query[b][w][d]) for this thread's 8 w, 8 b (packed).
    unsigned long long lq2[4][8];
    #pragma unroll
    for (int j = 0; j < 8; j++) {
        const int w = w0 + j;
        #pragma unroll
        for (int bp = 0; bp < 4; bp++) {
            float a = -flg2(query[((2 * bp)     * WNUM + w) * TDIM + d]);
            float b = -flg2(query[((2 * bp + 1) * WNUM + w) * TDIM + d]);
            lq2[bp][j] = pk2(a, b);
        }
    }

    // Staging: thread handles 16B chunks m = tid, tid+256 per k.
    const int w_a = tid >> 4,         c_a = tid & 15;
    const int w_b = (tid + 256) >> 4, c_b = (tid + 256) & 15;
    const int doff_a = (w_a * 64 + (((c_a + 2 * (w_a >> 3)) & 15) << 2)) * 4;
    const int doff_b = (w_b * 64 + (((c_b + 2 * (w_b >> 3)) & 15) << 2)) * 4;
    const long soff_a = ((long)w_a * TDIM + dt * DTILE + c_a * 4) * 4;
    const long soff_b = ((long)w_b * TDIM + dt * DTILE + c_b * 4) * 4;

    const char* kbase = (const char*)(qtext + (size_t)(chunk * KC) * (WNUM * TDIM));
    const unsigned tile_u32 = (unsigned)__cvta_generic_to_shared(tile);
    const long KROW = (long)WNUM * TDIM * 4;     // bytes per k

    auto issue_stage = [&](int s) {
        const int buf = s & 1;
        const char* src = kbase + (long)(s * STAGE_K) * KROW;
        const unsigned dbase = tile_u32 + buf * (STAGE_K * TILE_F * 4);
        #pragma unroll
        for (int ki = 0; ki < STAGE_K; ki++) {
            CP16(dbase + ki * (TILE_F * 4) + doff_a, src + ki * KROW + soff_a);
            CP16(dbase + ki * (TILE_F * 4) + doff_b, src + ki * KROW + soff_b);
        }
        asm volatile("cp.async.commit_group;");
    };

    issue_stage(0);

    float minv[4];
    int   mini[4];
    #pragma unroll
    for (int i = 0; i < 4; i++) { minv[i] = __int_as_float(0x7f800000); mini[i] = 0; }

    const int pbase = g * 512 + ((dl + 8 * g) & 63);   // LDS base (floats)

    #pragma unroll 1
    for (int s = 0; s < NSTAGE; s++) {
        if (s + 1 < NSTAGE) {
            issue_stage(s + 1);
            asm volatile("cp.async.wait_group 1;");
        } else {
            asm volatile("cp.async.wait_group 0;");
        }
        __syncthreads();

        const float* bufp = tile + (s & 1) * (STAGE_K * TILE_F);

        #pragma unroll
        for (int ki = 0; ki < STAGE_K; ki++) {
            const float* tp = bufp + ki * TILE_F;

            float x[8];
            #pragma unroll
            for (int j = 0; j < 8; j++) x[j] = tp[pbase + j * 64];

            float sacc = 0.0f;
            unsigned long long c2[4];
            #pragma unroll
            for (int bp = 0; bp < 4; bp++) c2[bp] = 0ull;

            #pragma unroll
            for (int j = 0; j < 8; j++) {
                const float xv = x[j];
                const float l  = flg2(xv);
                sacc = fmaf(xv, l, sacc);
                const unsigned long long xx = pk2(xv, xv);
                #pragma unroll
                for (int bp = 0; bp < 4; bp++)
                    c2[bp] = ffma2(xx, lq2[bp][j], c2[bp]);   // += x * (-lq)
            }

            // o_b = sacc + c_b  (c holds negated cross partials), packed add.
            const unsigned long long ss = pk2(sacc, sacc);
            float o[8];
            #pragma unroll
            for (int bp = 0; bp < 4; bp++) {
                unsigned long long o2 = fadd2(ss, c2[bp]);
                upk2(o2, o[2 * bp], o[2 * bp + 1]);
            }

            // r1 (xor 8): partners have opposite bh; each lane sends only the
            // half its partner keeps, receives the half it keeps.
            float h[4];
            #pragma unroll
            for (int i = 0; i < 4; i++) {
                const float send = bh ? o[i]     : o[4 + i];
                const float keep = bh ? o[4 + i] : o[i];
                h[i] = keep + __shfl_xor_sync(0xffffffffu, send, 8);
            }
            // r2 (xor 16): partner has the same b-half.
            #pragma unroll
            for (int i = 0; i < 4; i++)
                h[i] += __shfl_xor_sync(0xffffffffu, h[i], 16);

            const int kglob = chunk * KC + s * STAGE_K + ki;
            #pragma unroll
            for (int i = 0; i < 4; i++) {
                bool pmin = h[i] < minv[i];
                minv[i] = pmin ? h[i]  : minv[i];
                mini[i] = pmin ? kglob : mini[i];
            }
        }
        __syncthreads();
    }

    // Lanes g==0 hold b 0..3, g==1 hold b 4..7 (g==2,3 duplicates).
    if (g < 2) {
        #pragma unroll
        for (int i = 0; i < 4; i++) {
            g_pval[chunk][bh * 4 + i][d] = minv[i];
            g_pidx[chunk][bh * 4 + i][d] = mini[i];
        }
    }
}

// ---------------------------------------------------------------------------
// Phase 2a: reduce NCHUNK partial argmins -> g_idx[b*512+d].
// ---------------------------------------------------------------------------
__global__ __launch_bounds__(256)
void knw_phase2a() {
    const int bd = blockIdx.x * 256 + threadIdx.x;
    const int b  = bd >> 9;
    const int d  = bd & 511;
    float bv = __int_as_float(0x7f800000);
    int   bi = 0;
    #pragma unroll
    for (int c = 0; c < NCHUNK; c++) {
        float v = g_pval[c][b][d];
        int   i = g_pidx[c][b][d];
        if (v < bv) { bv = v; bi = i; }
    }
    g_idx[bd] = bi;
}

// ---------------------------------------------------------------------------
// Phase 2b: pure gather-copy, 2 float4 per thread.
// ---------------------------------------------------------------------------
#define TOT_F4 (BATCH * TDIM * FNUM * VDIM / 4)   // 6291456
__global__ __launch_bounds__(256)
void knw_phase2b(const float* __restrict__ qvideo, float* __restrict__ out) {
    const int t = blockIdx.x * 256 + threadIdx.x;
    const float4* __restrict__ src = (const float4*)qvideo;
    float4* __restrict__ dst = (float4*)out;
    #pragma unroll
    for (int u = 0; u < 2; u++) {
        const int gid = t + u * (TOT_F4 / 2);
        const int bd  = gid / 1536;
        const int r   = gid - bd * 1536;
        const int k   = g_idx[bd];
        dst[gid] = src[(size_t)k * 1536 + r];
    }
}

extern "C" void kernel_launch(void* const* d_in, const int* in_sizes, int n_in,
                              void* d_out, int out_size) {
    const float* query  = (const float*)d_in[0];   // [8, 32, 512]
    const float* qtext  = (const float*)d_in[1];   // [8192, 32, 512]
    const float* qvideo = (const float*)d_in[2];   // [8192, 12, 512]
    float* out = (float*)d_out;                    // [8, 512, 12, 512]

    cudaFuncSetAttribute(knw_phase1,
                         cudaFuncAttributeMaxDynamicSharedMemorySize, SMEM_BYTES);

    dim3 g1(NCHUNK, NDTILE);
    knw_phase1<<<g1, 256, SMEM_BYTES>>>(query, qtext);
    knw_phase2a<<<BATCH * TDIM / 256, 256>>>();
    knw_phase2b<<<(TOT_F4 / 2) / 256, 256>>>(qvideo, out);
}

// round 7
// speedup vs baseline: 2.0113x; 1.1557x over previous
#include <cuda_runtime.h>
#include <cstdint>

// Problem constants
#define KTOT  8192
#define WNUM  32
#define TDIM  512
#define FNUM  12
#define VDIM  512
#define BATCH 8

// Phase-1 tiling
#define KC      32                 // k per chunk
#define NCHUNK  (KTOT / KC)        // 256
#define DTILE   64
#define NDTILE  (TDIM / DTILE)     // 8
#define NWORK   37                 // workers per d-tile (296 = 8*37 CTAs total)
#define STAGE_K 4
#define SPC     (KC / STAGE_K)     // 8 stages per chunk
#define TILE_F  (WNUM * DTILE)     // 2048 floats = 8KB per k
#define SMEM_BYTES (2 * STAGE_K * TILE_F * 4)   // 64 KB

// Partial argmin results per (worker-residue, b, d)
__device__ float g_pval[NWORK][BATCH][TDIM];
__device__ int   g_pidx[NWORK][BATCH][TDIM];
__device__ int   g_idx[BATCH * TDIM];

// Exact-exponent log2: x = m*2^e (m in [1,2)), l = lg2.approx(m) + e.
// lg2.approx abs err on [1,2) ~1.5e-7; e exact. 1 MUFU, short chain.
__device__ __forceinline__ float flg2(float x) {
    int bi = __float_as_int(x);
    float m = __int_as_float((bi & 0x007fffff) | 0x3f800000);
    float e = (float)((bi >> 23) - 127);
    float lm;
    asm("lg2.approx.f32 %0, %1;" : "=f"(lm) : "f"(m));
    return lm + e;
}

__device__ __forceinline__ unsigned long long pk2(float a, float b) {
    unsigned long long r;
    asm("mov.b64 %0, {%1, %2};" : "=l"(r) : "f"(a), "f"(b));
    return r;
}
__device__ __forceinline__ void upk2(unsigned long long v, float& a, float& b) {
    asm("mov.b64 {%0, %1}, %2;" : "=f"(a), "=f"(b) : "l"(v));
}
__device__ __forceinline__ unsigned long long ffma2(unsigned long long a,
                                                    unsigned long long b,
                                                    unsigned long long c) {
    unsigned long long r;
    asm("fma.rn.f32x2 %0, %1, %2, %3;" : "=l"(r) : "l"(a), "l"(b), "l"(c));
    return r;
}
__device__ __forceinline__ unsigned long long fadd2(unsigned long long a,
                                                    unsigned long long b) {
    unsigned long long r;
    asm("add.rn.f32x2 %0, %1, %2;" : "=l"(r) : "l"(a), "l"(b));
    return r;
}

#define CP16(dst, src) \
    asm volatile("cp.async.cg.shared.global [%0], [%1], 16;" :: "r"(dst), "l"(src))

// ---------------------------------------------------------------------------
// Phase 1: 296 persistent workers = exactly 2 CTAs on each of 148 SMs.
// Worker w: dt = w/37 (d-tile of 64), r = w%37; processes chunks c = r,
// r+37, ... (<256) of KC=32 k each, in increasing k order, keeping a running
// per-(b,d) argmin in registers across all its chunks.
// Per stage: cp.async 4 k-rows of the [32w x 64d] tile into rotated shared
// memory (row w rotated by 8*(w>>3) floats -> conflict-free LDS).
// lane = g*8 + ds; thread owns one d, 8 w, 8 b; NEGATED query logs cached
// packed in registers. Per k: 8 LDS, 8 one-MUFU logs, 32 packed FMAs,
// o = sacc + c (packed), half-exchange butterfly, argmin.
// ---------------------------------------------------------------------------
__global__ __launch_bounds__(256, 2)
void knw_phase1(const float* __restrict__ query,
                const float* __restrict__ qtext) {
    extern __shared__ float tile[];              // [2][STAGE_K][TILE_F]

    const int wkr   = blockIdx.x;                // 0..295
    const int dt    = wkr / NWORK;
    const int r     = wkr - dt * NWORK;
    const int nch   = (r < 34) ? 7 : 6;          // 34*7 + 3*6 = 256 chunks
    const int nst   = nch * SPC;                 // stages for this worker

    const int tid   = threadIdx.x;
    const int lane  = tid & 31;
    const int g     = lane >> 3;
    const int ds    = lane & 7;
    const int w_id  = tid >> 5;
    const int dl    = w_id * 8 + ds;
    const int d     = dt * DTILE + dl;
    const int w0    = g * 8;
    const int bh    = g & 1;

    // NEGATED lg2(query[b][w][d]) for this thread's 8 w, 8 b (packed pairs).
    unsigned long long lq2[4][8];
    #pragma unroll
    for (int j = 0; j < 8; j++) {
        const int w = w0 + j;
        #pragma unroll
        for (int bp = 0; bp < 4; bp++) {
            float a = -flg2(query[((2 * bp)     * WNUM + w) * TDIM + d]);
            float b = -flg2(query[((2 * bp + 1) * WNUM + w) * TDIM + d]);
            lq2[bp][j] = pk2(a, b);
        }
    }

    // Staging: thread handles 16B chunks m = tid, tid+256 per k.
    const int w_a = tid >> 4,         c_a = tid & 15;
    const int w_b = (tid + 256) >> 4, c_b = (tid + 256) & 15;
    const int doff_a = (w_a * 64 + (((c_a + 2 * (w_a >> 3)) & 15) << 2)) * 4;
    const int doff_b = (w_b * 64 + (((c_b + 2 * (w_b >> 3)) & 15) << 2)) * 4;
    const long soff_a = ((long)w_a * TDIM + dt * DTILE + c_a * 4) * 4;
    const long soff_b = ((long)w_b * TDIM + dt * DTILE + c_b * 4) * 4;

    const unsigned tile_u32 = (unsigned)__cvta_generic_to_shared(tile);
    const long KROW = (long)WNUM * TDIM * 4;     // bytes per k

    // Stage s covers k = kglob0(s) .. +STAGE_K-1 with
    // kglob0(s) = (r + 37*(s>>3))*KC + (s&7)*STAGE_K.
    auto stage_k0 = [&](int s) {
        return (r + NWORK * (s >> 3)) * KC + (s & 7) * STAGE_K;
    };
    auto issue_stage = [&](int s) {
        const int buf = s & 1;
        const char* src = (const char*)qtext + (long)stage_k0(s) * KROW;
        const unsigned dbase = tile_u32 + buf * (STAGE_K * TILE_F * 4);
        #pragma unroll
        for (int ki = 0; ki < STAGE_K; ki++) {
            CP16(dbase + ki * (TILE_F * 4) + doff_a, src + ki * KROW + soff_a);
            CP16(dbase + ki * (TILE_F * 4) + doff_b, src + ki * KROW + soff_b);
        }
        asm volatile("cp.async.commit_group;");
    };

    issue_stage(0);

    float minv[4];
    int   mini[4];
    #pragma unroll
    for (int i = 0; i < 4; i++) { minv[i] = __int_as_float(0x7f800000); mini[i] = 0; }

    const int pbase = g * 512 + ((dl + 8 * g) & 63);   // LDS base (floats)

    #pragma unroll 1
    for (int s = 0; s < nst; s++) {
        if (s + 1 < nst) {
            issue_stage(s + 1);
            asm volatile("cp.async.wait_group 1;");
        } else {
            asm volatile("cp.async.wait_group 0;");
        }
        __syncthreads();

        const float* bufp = tile + (s & 1) * (STAGE_K * TILE_F);
        const int k0 = stage_k0(s);

        #pragma unroll
        for (int ki = 0; ki < STAGE_K; ki++) {
            const float* tp = bufp + ki * TILE_F;

            float x[8];
            #pragma unroll
            for (int j = 0; j < 8; j++) x[j] = tp[pbase + j * 64];

            float sacc = 0.0f;
            unsigned long long c2[4];
            #pragma unroll
            for (int bp = 0; bp < 4; bp++) c2[bp] = 0ull;

            #pragma unroll
            for (int j = 0; j < 8; j++) {
                const float xv = x[j];
                const float l  = flg2(xv);
                sacc = fmaf(xv, l, sacc);
                const unsigned long long xx = pk2(xv, xv);
                #pragma unroll
                for (int bp = 0; bp < 4; bp++)
                    c2[bp] = ffma2(xx, lq2[bp][j], c2[bp]);   // += x * (-lq)
            }

            // o_b = sacc + c_b (c holds negated cross partials), packed add.
            const unsigned long long ss = pk2(sacc, sacc);
            float o[8];
            #pragma unroll
            for (int bp = 0; bp < 4; bp++) {
                unsigned long long o2 = fadd2(ss, c2[bp]);
                upk2(o2, o[2 * bp], o[2 * bp + 1]);
            }

            // r1 (xor 8): partners have opposite bh; send only the partner's
            // half, keep own half.
            float h[4];
            #pragma unroll
            for (int i = 0; i < 4; i++) {
                const float send = bh ? o[i]     : o[4 + i];
                const float keep = bh ? o[4 + i] : o[i];
                h[i] = keep + __shfl_xor_sync(0xffffffffu, send, 8);
            }
            // r2 (xor 16): partner has the same b-half.
            #pragma unroll
            for (int i = 0; i < 4; i++)
                h[i] += __shfl_xor_sync(0xffffffffu, h[i], 16);

            const int kglob = k0 + ki;
            #pragma unroll
            for (int i = 0; i < 4; i++) {
                bool pmin = h[i] < minv[i];    // strict <: earliest k wins
                minv[i] = pmin ? h[i]  : minv[i];
                mini[i] = pmin ? kglob : mini[i];
            }
        }
        __syncthreads();
    }

    // Lanes g==0 hold b 0..3, g==1 hold b 4..7 (g==2,3 duplicates).
    if (g < 2) {
        #pragma unroll
        for (int i = 0; i < 4; i++) {
            g_pval[r][bh * 4 + i][d] = minv[i];
            g_pidx[r][bh * 4 + i][d] = mini[i];
        }
    }
}

// ---------------------------------------------------------------------------
// Phase 2a: reduce NWORK partial argmins -> g_idx[b*512+d].
// Workers hold interleaved k-sets, so break value ties by smaller k to match
// the reference's first-occurrence argmin.
// ---------------------------------------------------------------------------
__global__ __launch_bounds__(256)
void knw_phase2a() {
    const int bd = blockIdx.x * 256 + threadIdx.x;
    const int b  = bd >> 9;
    const int d  = bd & 511;
    float bv = __int_as_float(0x7f800000);
    int   bi = 0x7fffffff;
    #pragma unroll
    for (int r = 0; r < NWORK; r++) {
        float v = g_pval[r][b][d];
        int   i = g_pidx[r][b][d];
        if (v < bv || (v == bv && i < bi)) { bv = v; bi = i; }
    }
    g_idx[bd] = bi;
}

// ---------------------------------------------------------------------------
// Phase 2b: pure gather-copy, 4 float4 per thread (MLP to cover the
// dependent index->data chain).
// ---------------------------------------------------------------------------
#define TOT_F4 (BATCH * TDIM * FNUM * VDIM / 4)   // 6291456
#define GPT 4
__global__ __launch_bounds__(256)
void knw_phase2b(const float* __restrict__ qvideo, float* __restrict__ out) {
    const int t = blockIdx.x * 256 + threadIdx.x;
    const float4* __restrict__ src = (const float4*)qvideo;
    float4* __restrict__ dst = (float4*)out;
    #pragma unroll
    for (int u = 0; u < GPT; u++) {
        const int gid = t + u * (TOT_F4 / GPT);
        const int bd  = gid / 1536;
        const int rr  = gid - bd * 1536;
        const int k   = g_idx[bd];
        dst[gid] = src[(size_t)k * 1536 + rr];
    }
}

extern "C" void kernel_launch(void* const* d_in, const int* in_sizes, int n_in,
                              void* d_out, int out_size) {
    const float* query  = (const float*)d_in[0];   // [8, 32, 512]
    const float* qtext  = (const float*)d_in[1];   // [8192, 32, 512]
    const float* qvideo = (const float*)d_in[2];   // [8192, 12, 512]
    float* out = (float*)d_out;                    // [8, 512, 12, 512]

    cudaFuncSetAttribute(knw_phase1,
                         cudaFuncAttributeMaxDynamicSharedMemorySize, SMEM_BYTES);

    knw_phase1<<<NDTILE * NWORK, 256, SMEM_BYTES>>>(query, qtext);
    knw_phase2a<<<BATCH * TDIM / 256, 256>>>();
    knw_phase2b<<<(TOT_F4 / GPT) / 256, 256>>>(qvideo, out);
}

// round 8
// speedup vs baseline: 2.1628x; 1.0753x over previous
#include <cuda_runtime.h>
#include <cstdint>

// Problem constants
#define KTOT  8192
#define WNUM  32
#define TDIM  512
#define FNUM  12
#define VDIM  512
#define BATCH 8

// Phase-1 tiling
#define KC      32                 // k per chunk
#define NCHUNK  (KTOT / KC)        // 256
#define DTILE   64
#define NDTILE  (TDIM / DTILE)     // 8
#define NWORK   37                 // workers per d-tile (296 = 8*37 CTAs total)
#define STAGE_K 4
#define SPC     (KC / STAGE_K)     // 8 stages per chunk
#define TILE_F  (WNUM * DTILE)     // 2048 floats = 8KB per k
#define SMEM_BYTES (2 * STAGE_K * TILE_F * 4)   // 64 KB

// Partial argmin results per (worker-residue, b, d)
__device__ float g_pval[NWORK][BATCH][TDIM];
__device__ int   g_pidx[NWORK][BATCH][TDIM];
__device__ int   g_idx[BATCH * TDIM];

// Raw full-range MUFU log2: 1 op. Abs error <= ~2 ulp of result (~2e-6 at
// |l|~10); safe for the argmin by the flip-risk budget (margin ~30x).
__device__ __forceinline__ float flg2_fast(float x) {
    float l;
    asm("lg2.approx.f32 %0, %1;" : "=f"(l) : "f"(x));
    return l;
}

// Exact-exponent log2 (prologue only, for cached query logs):
// x = m*2^e (m in [1,2)), l = lg2.approx(m) + e.
__device__ __forceinline__ float flg2_exact(float x) {
    int bi = __float_as_int(x);
    float m = __int_as_float((bi & 0x007fffff) | 0x3f800000);
    float e = (float)((bi >> 23) - 127);
    float lm;
    asm("lg2.approx.f32 %0, %1;" : "=f"(lm) : "f"(m));
    return lm + e;
}

__device__ __forceinline__ unsigned long long pk2(float a, float b) {
    unsigned long long r;
    asm("mov.b64 %0, {%1, %2};" : "=l"(r) : "f"(a), "f"(b));
    return r;
}
__device__ __forceinline__ void upk2(unsigned long long v, float& a, float& b) {
    asm("mov.b64 {%0, %1}, %2;" : "=f"(a), "=f"(b) : "l"(v));
}
__device__ __forceinline__ unsigned long long ffma2(unsigned long long a,
                                                    unsigned long long b,
                                                    unsigned long long c) {
    unsigned long long r;
    asm("fma.rn.f32x2 %0, %1, %2, %3;" : "=l"(r) : "l"(a), "l"(b), "l"(c));
    return r;
}
__device__ __forceinline__ unsigned long long fadd2(unsigned long long a,
                                                    unsigned long long b) {
    unsigned long long r;
    asm("add.rn.f32x2 %0, %1, %2;" : "=l"(r) : "l"(a), "l"(b));
    return r;
}

#define CP16(dst, src) \
    asm volatile("cp.async.cg.shared.global [%0], [%1], 16;" :: "r"(dst), "l"(src))

// ---------------------------------------------------------------------------
// Phase 1: 296 persistent workers = exactly 2 CTAs on each of 148 SMs.
// Worker w: dt = w/37 (d-tile of 64), r = w%37; processes chunks c = r,
// r+37, ... (<256) of KC=32 k, keeping a running per-(b,d) argmin in
// registers across all its chunks.
// Per stage: cp.async 4 k-rows of the [32w x 64d] tile into rotated shared
// memory (row w rotated by 8*(w>>3) floats -> conflict-free LDS).
// lane = g*8 + ds; thread owns one d, 8 w, 8 b; NEGATED exact query logs
// cached packed in registers. Per k per element: 1 LDS + 1 MUFU log +
// 1 FMA (self) + 1 pack + 4 packed FMAs (8 b); then packed o = sacc + c,
// half-exchange butterfly, argmin.
// ---------------------------------------------------------------------------
__global__ __launch_bounds__(256, 2)
void knw_phase1(const float* __restrict__ query,
                const float* __restrict__ qtext) {
    extern __shared__ float tile[];              // [2][STAGE_K][TILE_F]

    const int wkr   = blockIdx.x;                // 0..295
    const int dt    = wkr / NWORK;
    const int r     = wkr - dt * NWORK;
    const int nch   = (r < 34) ? 7 : 6;          // 34*7 + 3*6 = 256 chunks
    const int nst   = nch * SPC;

    const int tid   = threadIdx.x;
    const int lane  = tid & 31;
    const int g     = lane >> 3;
    const int ds    = lane & 7;
    const int w_id  = tid >> 5;
    const int dl    = w_id * 8 + ds;
    const int d     = dt * DTILE + dl;
    const int w0    = g * 8;
    const int bh    = g & 1;

    // NEGATED exact lg2(query[b][w][d]) for this thread's 8 w, 8 b (packed).
    unsigned long long lq2[4][8];
    #pragma unroll
    for (int j = 0; j < 8; j++) {
        const int w = w0 + j;
        #pragma unroll
        for (int bp = 0; bp < 4; bp++) {
            float a = -flg2_exact(query[((2 * bp)     * WNUM + w) * TDIM + d]);
            float b = -flg2_exact(query[((2 * bp + 1) * WNUM + w) * TDIM + d]);
            lq2[bp][j] = pk2(a, b);
        }
    }

    // Staging: thread handles 16B chunks m = tid, tid+256 per k.
    const int w_a = tid >> 4,         c_a = tid & 15;
    const int w_b = (tid + 256) >> 4, c_b = (tid + 256) & 15;
    const int doff_a = (w_a * 64 + (((c_a + 2 * (w_a >> 3)) & 15) << 2)) * 4;
    const int doff_b = (w_b * 64 + (((c_b + 2 * (w_b >> 3)) & 15) << 2)) * 4;
    const long soff_a = ((long)w_a * TDIM + dt * DTILE + c_a * 4) * 4;
    const long soff_b = ((long)w_b * TDIM + dt * DTILE + c_b * 4) * 4;

    const unsigned tile_u32 = (unsigned)__cvta_generic_to_shared(tile);
    const long KROW = (long)WNUM * TDIM * 4;     // bytes per k

    auto stage_k0 = [&](int s) {
        return (r + NWORK * (s >> 3)) * KC + (s & 7) * STAGE_K;
    };
    auto issue_stage = [&](int s) {
        const int buf = s & 1;
        const char* src = (const char*)qtext + (long)stage_k0(s) * KROW;
        const unsigned dbase = tile_u32 + buf * (STAGE_K * TILE_F * 4);
        #pragma unroll
        for (int ki = 0; ki < STAGE_K; ki++) {
            CP16(dbase + ki * (TILE_F * 4) + doff_a, src + ki * KROW + soff_a);
            CP16(dbase + ki * (TILE_F * 4) + doff_b, src + ki * KROW + soff_b);
        }
        asm volatile("cp.async.commit_group;");
    };

    issue_stage(0);

    float minv[4];
    int   mini[4];
    #pragma unroll
    for (int i = 0; i < 4; i++) { minv[i] = __int_as_float(0x7f800000); mini[i] = 0; }

    const int pbase = g * 512 + ((dl + 8 * g) & 63);   // LDS base (floats)

    #pragma unroll 1
    for (int s = 0; s < nst; s++) {
        if (s + 1 < nst) {
            issue_stage(s + 1);
            asm volatile("cp.async.wait_group 1;");
        } else {
            asm volatile("cp.async.wait_group 0;");
        }
        __syncthreads();

        const float* bufp = tile + (s & 1) * (STAGE_K * TILE_F);
        const int k0 = stage_k0(s);

        #pragma unroll
        for (int ki = 0; ki < STAGE_K; ki++) {
            const float* tp = bufp + ki * TILE_F;

            float x[8];
            #pragma unroll
            for (int j = 0; j < 8; j++) x[j] = tp[pbase + j * 64];

            float sacc = 0.0f;
            unsigned long long c2[4];
            #pragma unroll
            for (int bp = 0; bp < 4; bp++) c2[bp] = 0ull;

            #pragma unroll
            for (int j = 0; j < 8; j++) {
                const float xv = x[j];
                const float l  = flg2_fast(xv);          // 1 MUFU
                sacc = fmaf(xv, l, sacc);
                const unsigned long long xx = pk2(xv, xv);
                #pragma unroll
                for (int bp = 0; bp < 4; bp++)
                    c2[bp] = ffma2(xx, lq2[bp][j], c2[bp]);   // += x * (-lq)
            }

            // o_b = sacc + c_b (c holds negated cross partials), packed add.
            const unsigned long long ss = pk2(sacc, sacc);
            float o[8];
            #pragma unroll
            for (int bp = 0; bp < 4; bp++) {
                unsigned long long o2 = fadd2(ss, c2[bp]);
                upk2(o2, o[2 * bp], o[2 * bp + 1]);
            }

            // r1 (xor 8): partners have opposite bh; send the partner's half,
            // keep own half.
            float h[4];
            #pragma unroll
            for (int i = 0; i < 4; i++) {
                const float send = bh ? o[i]     : o[4 + i];
                const float keep = bh ? o[4 + i] : o[i];
                h[i] = keep + __shfl_xor_sync(0xffffffffu, send, 8);
            }
            // r2 (xor 16): partner has the same b-half.
            #pragma unroll
            for (int i = 0; i < 4; i++)
                h[i] += __shfl_xor_sync(0xffffffffu, h[i], 16);

            const int kglob = k0 + ki;
            #pragma unroll
            for (int i = 0; i < 4; i++) {
                bool pmin = h[i] < minv[i];    // strict <: earliest k wins
                minv[i] = pmin ? h[i]  : minv[i];
                mini[i] = pmin ? kglob : mini[i];
            }
        }
        __syncthreads();
    }

    // Lanes g==0 hold b 0..3, g==1 hold b 4..7 (g==2,3 duplicates).
    if (g < 2) {
        #pragma unroll
        for (int i = 0; i < 4; i++) {
            g_pval[r][bh * 4 + i][d] = minv[i];
            g_pidx[r][bh * 4 + i][d] = mini[i];
        }
    }
}

// ---------------------------------------------------------------------------
// Phase 2a: reduce NWORK partial argmins -> g_idx[b*512+d].
// Workers hold interleaved k-sets: break value ties by smaller k to match
// the reference's first-occurrence argmin.
// ---------------------------------------------------------------------------
__global__ __launch_bounds__(256)
void knw_phase2a() {
    const int bd = blockIdx.x * 256 + threadIdx.x;
    const int b  = bd >> 9;
    const int d  = bd & 511;
    float bv = __int_as_float(0x7f800000);
    int   bi = 0x7fffffff;
    #pragma unroll
    for (int r = 0; r < NWORK; r++) {
        float v = g_pval[r][b][d];
        int   i = g_pidx[r][b][d];
        if (v < bv || (v == bv && i < bi)) { bv = v; bi = i; }
    }
    g_idx[bd] = bi;
}

// ---------------------------------------------------------------------------
// Phase 2b: pure gather-copy, 8 float4 per thread (MLP to cover the
// dependent index->data chain; strided segments keep full coalescing).
// ---------------------------------------------------------------------------
#define TOT_F4 (BATCH * TDIM * FNUM * VDIM / 4)   // 6291456
#define GPT 8
__global__ __launch_bounds__(256)
void knw_phase2b(const float* __restrict__ qvideo, float* __restrict__ out) {
    const int t = blockIdx.x * 256 + threadIdx.x;
    const float4* __restrict__ src = (const float4*)qvideo;
    float4* __restrict__ dst = (float4*)out;
    #pragma unroll
    for (int u = 0; u < GPT; u++) {
        const int gid = t + u * (TOT_F4 / GPT);
        const int bd  = gid / 1536;
        const int rr  = gid - bd * 1536;
        const int k   = g_idx[bd];
        dst[gid] = src[(size_t)k * 1536 + rr];
    }
}

extern "C" void kernel_launch(void* const* d_in, const int* in_sizes, int n_in,
                              void* d_out, int out_size) {
    const float* query  = (const float*)d_in[0];   // [8, 32, 512]
    const float* qtext  = (const float*)d_in[1];   // [8192, 32, 512]
    const float* qvideo = (const float*)d_in[2];   // [8192, 12, 512]
    float* out = (float*)d_out;                    // [8, 512, 12, 512]

    cudaFuncSetAttribute(knw_phase1,
                         cudaFuncAttributeMaxDynamicSharedMemorySize, SMEM_BYTES);

    knw_phase1<<<NDTILE * NWORK, 256, SMEM_BYTES>>>(query, qtext);
    knw_phase2a<<<BATCH * TDIM / 256, 256>>>();
    knw_phase2b<<<(TOT_F4 / GPT) / 256, 256>>>(qvideo, out);
}

// round 9
// speedup vs baseline: 2.2166x; 1.0249x over previous
#include <cuda_runtime.h>
#include <cstdint>

// Problem constants
#define KTOT  8192
#define WNUM  32
#define TDIM  512
#define FNUM  12
#define VDIM  512
#define BATCH 8

// Phase-1 tiling
#define KC      32                 // k per chunk
#define NCHUNK  (KTOT / KC)        // 256
#define DTILE   64
#define NDTILE  (TDIM / DTILE)     // 8
#define NWORK   37                 // workers per d-tile (296 = 8*37 CTAs)
#define STAGE_K 4
#define SPC     (KC / STAGE_K)     // 8 stages per chunk
#define TILE_F  (WNUM * DTILE)     // 2048 floats = 8KB per k
#define SMEM_BYTES (2 * STAGE_K * TILE_F * 4)   // 64 KB

// Partial argmin results per (worker-residue, b, d)
__device__ float g_pval[NWORK][BATCH][TDIM];
__device__ int   g_pidx[NWORK][BATCH][TDIM];
__device__ int   g_idx[BATCH * TDIM];

// Raw full-range MUFU log2 (validated: rel_err 0.0 across rounds).
__device__ __forceinline__ float flg2_fast(float x) {
    float l;
    asm("lg2.approx.f32 %0, %1;" : "=f"(l) : "f"(x));
    return l;
}

// Exact-exponent log2 (prologue only, cached query logs).
__device__ __forceinline__ float flg2_exact(float x) {
    int bi = __float_as_int(x);
    float m = __int_as_float((bi & 0x007fffff) | 0x3f800000);
    float e = (float)((bi >> 23) - 127);
    float lm;
    asm("lg2.approx.f32 %0, %1;" : "=f"(lm) : "f"(m));
    return lm + e;
}

__device__ __forceinline__ unsigned long long pk2(float a, float b) {
    unsigned long long r;
    asm("mov.b64 %0, {%1, %2};" : "=l"(r) : "f"(a), "f"(b));
    return r;
}
__device__ __forceinline__ void upk2(unsigned long long v, float& a, float& b) {
    asm("mov.b64 {%0, %1}, %2;" : "=f"(a), "=f"(b) : "l"(v));
}
__device__ __forceinline__ unsigned long long ffma2(unsigned long long a,
                                                    unsigned long long b,
                                                    unsigned long long c) {
    unsigned long long r;
    asm("fma.rn.f32x2 %0, %1, %2, %3;" : "=l"(r) : "l"(a), "l"(b), "l"(c));
    return r;
}
__device__ __forceinline__ unsigned long long fadd2(unsigned long long a,
                                                    unsigned long long b) {
    unsigned long long r;
    asm("add.rn.f32x2 %0, %1, %2;" : "=l"(r) : "l"(a), "l"(b));
    return r;
}

#define CP16(dst, src) \
    asm volatile("cp.async.cg.shared.global [%0], [%1], 16;" :: "r"(dst), "l"(src))

// ---------------------------------------------------------------------------
// Phase 1: 296 persistent workers = 2 CTAs on each of 148 SMs.
// Worker w: dt = w/37 (d-tile of 64), r = w%37; chunks c = r, r+37, ... of
// KC=32 k each; running per-(b,d) argmin in registers.
// Per stage: cp.async 4 k-rows of the [32w x 64d] tile into rotated shared
// memory (row w rotated by 8*(w>>3) floats -> conflict-free LDS).
// lane = g*8 + ds; thread owns one d, 8 w; NEGATED exact query logs cached
// packed over b-pairs. Per k: 8 LDS + 8 MUFU + 8 FMA + 8 mov + 32 FFMA2,
// then a fully-PACKED halving butterfly: r1 (xor8) exchanges 2 b-pairs,
// r2 (xor16) exchanges 1; each lane ends owning b-pair (2*bh + bh2) and
// argmins only 2 scalars.
// ---------------------------------------------------------------------------
__global__ __launch_bounds__(256, 2)
void knw_phase1(const float* __restrict__ query,
                const float* __restrict__ qtext) {
    extern __shared__ float tile[];              // [2][STAGE_K][TILE_F]

    const int wkr   = blockIdx.x;                // 0..295
    const int dt    = wkr / NWORK;
    const int r     = wkr - dt * NWORK;
    const int nch   = (r < 34) ? 7 : 6;          // 34*7 + 3*6 = 256 chunks
    const int nst   = nch * SPC;

    const int tid   = threadIdx.x;
    const int lane  = tid & 31;
    const int g     = lane >> 3;
    const int ds    = lane & 7;
    const int w_id  = tid >> 5;
    const int dl    = w_id * 8 + ds;
    const int d     = dt * DTILE + dl;
    const int w0    = g * 8;
    const int bh    = g & 1;                     // g bit 0 (xor-8 partner flips)
    const int bh2   = (g >> 1) & 1;              // g bit 1 (xor-16 partner flips)
    const int bbase = 4 * bh + 2 * bh2;          // this lane's final b-pair base

    // NEGATED exact lg2(query[b][w][d]), 8 w x 8 b packed over b-pairs.
    unsigned long long lq2[4][8];
    #pragma unroll
    for (int j = 0; j < 8; j++) {
        const int w = w0 + j;
        #pragma unroll
        for (int bp = 0; bp < 4; bp++) {
            float a = -flg2_exact(query[((2 * bp)     * WNUM + w) * TDIM + d]);
            float b = -flg2_exact(query[((2 * bp + 1) * WNUM + w) * TDIM + d]);
            lq2[bp][j] = pk2(a, b);
        }
    }

    // Staging: thread handles 16B chunks m = tid, tid+256 per k.
    const int w_a = tid >> 4,         c_a = tid & 15;
    const int w_b = (tid + 256) >> 4, c_b = (tid + 256) & 15;
    const int doff_a = (w_a * 64 + (((c_a + 2 * (w_a >> 3)) & 15) << 2)) * 4;
    const int doff_b = (w_b * 64 + (((c_b + 2 * (w_b >> 3)) & 15) << 2)) * 4;
    const long soff_a = ((long)w_a * TDIM + dt * DTILE + c_a * 4) * 4;
    const long soff_b = ((long)w_b * TDIM + dt * DTILE + c_b * 4) * 4;

    const unsigned tile_u32 = (unsigned)__cvta_generic_to_shared(tile);
    const long KROW = (long)WNUM * TDIM * 4;     // bytes per k

    auto stage_k0 = [&](int s) {
        return (r + NWORK * (s >> 3)) * KC + (s & 7) * STAGE_K;
    };
    auto issue_stage = [&](int s) {
        const int buf = s & 1;
        const char* src = (const char*)qtext + (long)stage_k0(s) * KROW;
        const unsigned dbase = tile_u32 + buf * (STAGE_K * TILE_F * 4);
        #pragma unroll
        for (int ki = 0; ki < STAGE_K; ki++) {
            CP16(dbase + ki * (TILE_F * 4) + doff_a, src + ki * KROW + soff_a);
            CP16(dbase + ki * (TILE_F * 4) + doff_b, src + ki * KROW + soff_b);
        }
        asm volatile("cp.async.commit_group;");
    };

    issue_stage(0);

    float minv0 = __int_as_float(0x7f800000), minv1 = minv0;
    int   mini0 = 0, mini1 = 0;

    const int pbase = g * 512 + ((dl + 8 * g) & 63);   // LDS base (floats)

    #pragma unroll 1
    for (int s = 0; s < nst; s++) {
        if (s + 1 < nst) {
            issue_stage(s + 1);
            asm volatile("cp.async.wait_group 1;");
        } else {
            asm volatile("cp.async.wait_group 0;");
        }
        __syncthreads();

        const float* bufp = tile + (s & 1) * (STAGE_K * TILE_F);
        const int k0 = stage_k0(s);

        #pragma unroll
        for (int ki = 0; ki < STAGE_K; ki++) {
            const float* tp = bufp + ki * TILE_F;

            float x[8];
            #pragma unroll
            for (int j = 0; j < 8; j++) x[j] = tp[pbase + j * 64];

            float sacc = 0.0f;
            unsigned long long c2[4];
            #pragma unroll
            for (int bp = 0; bp < 4; bp++) c2[bp] = 0ull;

            #pragma unroll
            for (int j = 0; j < 8; j++) {
                const float xv = x[j];
                const float l  = flg2_fast(xv);          // 1 MUFU
                sacc = fmaf(xv, l, sacc);
                const unsigned long long xx = pk2(xv, xv);
                #pragma unroll
                for (int bp = 0; bp < 4; bp++)
                    c2[bp] = ffma2(xx, lq2[bp][j], c2[bp]);   // += x * (-lq)
            }

            // o2[bp] = sacc + c_bp (packed b-pairs; c holds negated cross).
            const unsigned long long ss = pk2(sacc, sacc);
            unsigned long long o2[4];
            #pragma unroll
            for (int bp = 0; bp < 4; bp++) o2[bp] = fadd2(ss, c2[bp]);

            // r1 (xor 8): partner has opposite bh. Keep this half's 2 pairs
            // (bh=0 -> pairs {0,1}=b0..3, bh=1 -> pairs {2,3}=b4..7), send
            // the other 2.
            unsigned long long s0 = bh ? o2[0] : o2[2];
            unsigned long long s1 = bh ? o2[1] : o2[3];
            unsigned long long k0p = bh ? o2[2] : o2[0];
            unsigned long long k1p = bh ? o2[3] : o2[1];
            unsigned long long h0 = fadd2(k0p, __shfl_xor_sync(0xffffffffu, s0, 8));
            unsigned long long h1 = fadd2(k1p, __shfl_xor_sync(0xffffffffu, s1, 8));

            // r2 (xor 16): partner has same bh, opposite bh2. Keep one pair
            // (bh2 selects), send the other. Lane ends with pair 2*bh+bh2.
            unsigned long long s2 = bh2 ? h0 : h1;
            unsigned long long k2 = bh2 ? h1 : h0;
            unsigned long long hf = fadd2(k2, __shfl_xor_sync(0xffffffffu, s2, 16));

            float ha, hb;
            upk2(hf, ha, hb);

            const int kglob = k0 + ki;
            bool p0 = ha < minv0;               // strict <: earliest k wins
            bool p1 = hb < minv1;
            minv0 = fminf(ha, minv0);
            minv1 = fminf(hb, minv1);
            mini0 = p0 ? kglob : mini0;
            mini1 = p1 ? kglob : mini1;
        }
        __syncthreads();
    }

    // Every lane owns b-pair (bbase, bbase+1) for its d. 32 lanes cover
    // 8 d x 8 b exactly once.
    g_pval[r][bbase][d]     = minv0;
    g_pidx[r][bbase][d]     = mini0;
    g_pval[r][bbase + 1][d] = minv1;
    g_pidx[r][bbase + 1][d] = mini1;
}

// ---------------------------------------------------------------------------
// Phase 2a: reduce NWORK partial argmins -> g_idx[b*512+d].
// Workers hold interleaved k-sets: break value ties by smaller k.
// ---------------------------------------------------------------------------
__global__ __launch_bounds__(256)
void knw_phase2a() {
    const int bd = blockIdx.x * 256 + threadIdx.x;
    const int b  = bd >> 9;
    const int d  = bd & 511;
    float bv = __int_as_float(0x7f800000);
    int   bi = 0x7fffffff;
    #pragma unroll
    for (int r = 0; r < NWORK; r++) {
        float v = g_pval[r][b][d];
        int   i = g_pidx[r][b][d];
        if (v < bv || (v == bv && i < bi)) { bv = v; bi = i; }
    }
    g_idx[bd] = bi;
}

// ---------------------------------------------------------------------------
// Phase 2b: one CTA per (b,d) row. bd = blockIdx.x (no division), index
// loaded once (L1 broadcast), 6 independent LDG.128 per thread, streaming
// stores (__stcs) keep the gathered qvideo rows resident in L2.
// ---------------------------------------------------------------------------
#define ROW_F4 (FNUM * VDIM / 4)   // 1536 float4 per row
__global__ __launch_bounds__(256)
void knw_phase2b(const float* __restrict__ qvideo, float* __restrict__ out) {
    const int bd = blockIdx.x;                   // 0..4095
    const int k  = g_idx[bd];
    const float4* __restrict__ src = (const float4*)qvideo + (size_t)k * ROW_F4;
    float4* __restrict__ dst = (float4*)out + (size_t)bd * ROW_F4;
    const int t = threadIdx.x;
    float4 v[6];
    #pragma unroll
    for (int u = 0; u < 6; u++) v[u] = src[t + u * 256];
    #pragma unroll
    for (int u = 0; u < 6; u++) __stcs(&dst[t + u * 256], v[u]);
}

extern "C" void kernel_launch(void* const* d_in, const int* in_sizes, int n_in,
                              void* d_out, int out_size) {
    const float* query  = (const float*)d_in[0];   // [8, 32, 512]
    const float* qtext  = (const float*)d_in[1];   // [8192, 32, 512]
    const float* qvideo = (const float*)d_in[2];   // [8192, 12, 512]
    float* out = (float*)d_out;                    // [8, 512, 12, 512]

    cudaFuncSetAttribute(knw_phase1,
                         cudaFuncAttributeMaxDynamicSharedMemorySize, SMEM_BYTES);

    knw_phase1<<<NDTILE * NWORK, 256, SMEM_BYTES>>>(query, qtext);
    knw_phase2a<<<BATCH * TDIM / 256, 256>>>();
    knw_phase2b<<<BATCH * TDIM, 256>>>(qvideo, out);
}